// round 4
// baseline (speedup 1.0000x reference)
#include <cuda_runtime.h>
#include <math.h>

#define B_    16
#define L_    512
#define HID_  768
#define HEADS_ 12
#define M_    4
#define EMB_  768
#define BLK_  8
#define NER_  6
#define NCLS_ 97
#define XDIM_ 1542   // 2*HID + NER
#define XPAD_ 1544

// Scratch (allocation-free rule: __device__ globals)
__device__ float g_HT[B_][L_];            // normalized ht_att
__device__ float g_X[2][B_][XPAD_];       // concat inputs [hs|rs|ner] for e=0, [ts|rs|ner] for e=1
__device__ float g_RSp[4][B_][HID_];      // rs partials (L split 4)
__device__ float g_S2[2][B_][EMB_];       // hs2 / ts2

// ---------------------------------------------------------------------------
// K1: per-batch gather: logsumexp entity embeddings + ht_att (normalized)
// grid = B_, block = 512 (one thread per l for the attention part)
// ---------------------------------------------------------------------------
__global__ void k1_gather(const float* __restrict__ seq,
                          const float* __restrict__ attn,
                          const int*   __restrict__ epos,
                          const float* __restrict__ hs_ner,
                          const float* __restrict__ ts_ner)
{
    int b = blockIdx.x, tid = threadIdx.x;
    __shared__ int st[2][M_];
    __shared__ float ht[L_];
    __shared__ float red[512];

    if (tid < 2 * M_) st[tid >> 2][tid & 3] = epos[b * 2 * M_ + tid] + 1;
    __syncthreads();

    // ent_emb = logsumexp over M mentions
    for (int it = tid; it < 2 * HID_; it += 512) {
        int e = it / HID_, d = it - e * HID_;
        float v0 = seq[((size_t)b * L_ + st[e][0]) * HID_ + d];
        float v1 = seq[((size_t)b * L_ + st[e][1]) * HID_ + d];
        float v2 = seq[((size_t)b * L_ + st[e][2]) * HID_ + d];
        float v3 = seq[((size_t)b * L_ + st[e][3]) * HID_ + d];
        float mx = fmaxf(fmaxf(v0, v1), fmaxf(v2, v3));
        float s  = expf(v0 - mx) + expf(v1 - mx) + expf(v2 - mx) + expf(v3 - mx);
        g_X[e][b][d] = mx + logf(s);
    }
    // ner tags into concat slots [1536..1541]
    if (tid < 2 * NER_) {
        int e = tid / NER_, j = tid - e * NER_;
        g_X[e][b][2 * HID_ + j] = e ? ts_ner[b * NER_ + j] : hs_ner[b * NER_ + j];
    }

    // ht_att: per l, mean over heads of (mean_m h_att * mean_m t_att)
    {
        int l = tid;  // 512 threads == L
        float acc = 0.f;
        const float* ab = attn + (size_t)b * HEADS_ * L_ * L_;
        #pragma unroll
        for (int h = 0; h < HEADS_; h++) {
            const float* ah = ab + (size_t)h * L_ * L_;
            float ha = ah[st[0][0] * L_ + l] + ah[st[0][1] * L_ + l]
                     + ah[st[0][2] * L_ + l] + ah[st[0][3] * L_ + l];
            float ta = ah[st[1][0] * L_ + l] + ah[st[1][1] * L_ + l]
                     + ah[st[1][2] * L_ + l] + ah[st[1][3] * L_ + l];
            acc += ha * ta;
        }
        acc *= (0.25f * 0.25f) / (float)HEADS_;
        ht[l]  = acc;
        red[tid] = acc;
    }
    __syncthreads();
    for (int s = 256; s > 0; s >>= 1) {
        if (tid < s) red[tid] += red[tid + s];
        __syncthreads();
    }
    float inv = 1.f / (red[0] + 1e-5f);
    g_HT[b][tid] = ht[tid] * inv;
}

// ---------------------------------------------------------------------------
// K2: rs partials: rs_part[z][b][d] = sum_{l in chunk z} seq[b,l,d] * ht[b,l]
// grid = (B, HID/256, 4), block = 256
// ---------------------------------------------------------------------------
__global__ void k2_rs(const float* __restrict__ seq)
{
    int b = blockIdx.x;
    int d = blockIdx.y * 256 + threadIdx.x;
    int z = blockIdx.z;
    __shared__ float ht[128];
    int l0 = z * 128;
    if (threadIdx.x < 128) ht[threadIdx.x] = g_HT[b][l0 + threadIdx.x];
    __syncthreads();

    const float* p = seq + ((size_t)b * L_ + l0) * HID_ + d;
    float acc = 0.f;
    #pragma unroll 8
    for (int l = 0; l < 128; l++) acc += p[(size_t)l * HID_] * ht[l];
    g_RSp[z][b][d] = acc;
}

// K2b: deterministic 4-way reduce, scatter rs into both concat buffers
// grid = 48, block = 256  (16*768 = 12288 elements)
__global__ void k2b_reduce()
{
    int i = blockIdx.x * 256 + threadIdx.x;
    int b = i / HID_, d = i - b * HID_;
    float v = g_RSp[0][b][d] + g_RSp[1][b][d] + g_RSp[2][b][d] + g_RSp[3][b][d];
    g_X[0][b][HID_ + d] = v;
    g_X[1][b][HID_ + d] = v;
}

// ---------------------------------------------------------------------------
// K3: hs2/ts2 = tanh(X @ W.T + bias). Tiled 16 rows x 16 batches per block so
// each W row is read from DRAM exactly once.
// grid = (EMB/16, 2), block = 256 (r = tid/16 -> output row, c = tid%16 -> batch)
// ---------------------------------------------------------------------------
__global__ void k3_proj(const float* __restrict__ Wh, const float* __restrict__ bh,
                        const float* __restrict__ Wt, const float* __restrict__ bt)
{
    int e    = blockIdx.y;
    int row0 = blockIdx.x * 16;
    const float* W    = e ? Wt : Wh;
    const float* bias = e ? bt : bh;
    int tid = threadIdx.x;
    int r = tid >> 4, c = tid & 15;

    __shared__ float Ws[16][129];
    __shared__ float Xs[16][129];

    float acc = 0.f;
    for (int j0 = 0; j0 < XDIM_; j0 += 128) {
        for (int t = tid; t < 16 * 128; t += 256) {
            int rr = t >> 7, jj = t & 127;
            int j = j0 + jj;
            float wv = 0.f, xv = 0.f;
            if (j < XDIM_) {
                wv = W[(size_t)(row0 + rr) * XDIM_ + j];
                xv = g_X[e][rr][j];           // rr doubles as batch index here
            }
            Ws[rr][jj] = wv;
            Xs[rr][jj] = xv;
        }
        __syncthreads();
        #pragma unroll
        for (int jj = 0; jj < 128; jj++) acc += Ws[r][jj] * Xs[c][jj];
        __syncthreads();
    }
    g_S2[e][c][row0 + r] = tanhf(acc + bias[row0 + r]);
}

// ---------------------------------------------------------------------------
// K4: fused bilinear outer-product + logits = bl @ Wb.T + bb
// grid = (NCLS, 4 batch-groups), block = 256
// ---------------------------------------------------------------------------
__global__ void k4_logits(const float* __restrict__ Wb, const float* __restrict__ bbias,
                          float* __restrict__ out)
{
    int c  = blockIdx.x;   // class
    int bg = blockIdx.y;   // batch group of 4
    int tid = threadIdx.x;

    __shared__ float hs[4][EMB_];
    __shared__ float ts[4][EMB_];
    for (int t = tid; t < 4 * EMB_; t += 256) {
        int bi = t / EMB_, d = t - bi * EMB_;
        hs[bi][d] = g_S2[0][bg * 4 + bi][d];
        ts[bi][d] = g_S2[1][bg * 4 + bi][d];
    }
    __syncthreads();

    float a0 = 0.f, a1 = 0.f, a2 = 0.f, a3 = 0.f;
    const float* wr = Wb + (size_t)c * EMB_ * BLK_;
    for (int j = tid; j < EMB_ * BLK_; j += 256) {
        float w = wr[j];
        int g = j >> 6, rem = j & 63, i = rem >> 3, jj = rem & 7;
        int hi = g * 8 + i, ti = g * 8 + jj;
        a0 += w * hs[0][hi] * ts[0][ti];
        a1 += w * hs[1][hi] * ts[1][ti];
        a2 += w * hs[2][hi] * ts[2][ti];
        a3 += w * hs[3][hi] * ts[3][ti];
    }

    __shared__ float red[4][256];
    red[0][tid] = a0; red[1][tid] = a1; red[2][tid] = a2; red[3][tid] = a3;
    __syncthreads();
    for (int s = 128; s > 0; s >>= 1) {
        if (tid < s) {
            red[0][tid] += red[0][tid + s];
            red[1][tid] += red[1][tid + s];
            red[2][tid] += red[2][tid + s];
            red[3][tid] += red[3][tid + s];
        }
        __syncthreads();
    }
    if (tid < 4)
        out[(size_t)(bg * 4 + tid) * NCLS_ + c] = red[tid][0] + bbias[c];
}

// ---------------------------------------------------------------------------
extern "C" void kernel_launch(void* const* d_in, const int* in_sizes, int n_in,
                              void* d_out, int out_size)
{
    const float* seq  = (const float*)d_in[0];
    const float* attn = (const float*)d_in[1];
    const int*   epos = (const int*)  d_in[2];
    const float* hsn  = (const float*)d_in[3];
    const float* tsn  = (const float*)d_in[4];
    const float* Wh   = (const float*)d_in[5];
    const float* bh   = (const float*)d_in[6];
    const float* Wt   = (const float*)d_in[7];
    const float* bt   = (const float*)d_in[8];
    const float* Wb   = (const float*)d_in[9];
    const float* bb   = (const float*)d_in[10];
    float* out = (float*)d_out;

    k1_gather<<<B_, 512>>>(seq, attn, epos, hsn, tsn);
    k2_rs<<<dim3(B_, HID_ / 256, 4), 256>>>(seq);
    k2b_reduce<<<48, 256>>>();
    k3_proj<<<dim3(EMB_ / 16, 2), 256>>>(Wh, bh, Wt, bt);
    k4_logits<<<dim3(NCLS_, 4), 256>>>(Wb, bb, out);
}

// round 7
// speedup vs baseline: 1.3287x; 1.3287x over previous
#include <cuda_runtime.h>
#include <math.h>

#define B_    16
#define L_    512
#define HID_  768
#define HEADS_ 12
#define M_    4
#define EMB_  768
#define BLK_  8
#define NER_  6
#define NCLS_ 97
#define XDIM_ 1542   // 2*HID + NER
#define XPAD_ 1544

// Scratch (allocation-free rule: __device__ globals)
__device__ float g_HT[B_][L_];            // normalized ht_att
__device__ float g_X[2][B_][XPAD_];       // concat inputs [hs|rs|ner] for e=0, [ts|rs|ner] for e=1
__device__ float g_RSp[4][B_][HID_];      // rs partials (L split 4)
__device__ float g_S2[2][B_][EMB_];       // hs2 / ts2

// ---------------------------------------------------------------------------
// K1: per-batch gather: logsumexp entity embeddings + ht_att (normalized)
// grid = B_, block = 512
// ---------------------------------------------------------------------------
__global__ void k1_gather(const float* __restrict__ seq,
                          const float* __restrict__ attn,
                          const int*   __restrict__ epos,
                          const float* __restrict__ hs_ner,
                          const float* __restrict__ ts_ner)
{
    int b = blockIdx.x, tid = threadIdx.x;
    __shared__ int st[2][M_];
    __shared__ float ht[L_];
    __shared__ float red[512];

    if (tid < 2 * M_) st[tid >> 2][tid & 3] = epos[b * 2 * M_ + tid] + 1;
    __syncthreads();

    for (int it = tid; it < 2 * HID_; it += 512) {
        int e = it / HID_, d = it - e * HID_;
        float v0 = seq[((size_t)b * L_ + st[e][0]) * HID_ + d];
        float v1 = seq[((size_t)b * L_ + st[e][1]) * HID_ + d];
        float v2 = seq[((size_t)b * L_ + st[e][2]) * HID_ + d];
        float v3 = seq[((size_t)b * L_ + st[e][3]) * HID_ + d];
        float mx = fmaxf(fmaxf(v0, v1), fmaxf(v2, v3));
        float s  = expf(v0 - mx) + expf(v1 - mx) + expf(v2 - mx) + expf(v3 - mx);
        g_X[e][b][d] = mx + logf(s);
    }
    if (tid < 2 * NER_) {
        int e = tid / NER_, j = tid - e * NER_;
        g_X[e][b][2 * HID_ + j] = e ? ts_ner[b * NER_ + j] : hs_ner[b * NER_ + j];
    }
    // zero the float4 pad tail of X so k3 vector reads are safe
    if (tid < 4) {
        int e = tid >> 1, j = tid & 1;
        g_X[e][b][XDIM_ + j] = 0.f;
    }

    {
        int l = tid;
        float acc = 0.f;
        const float* ab = attn + (size_t)b * HEADS_ * L_ * L_;
        #pragma unroll
        for (int h = 0; h < HEADS_; h++) {
            const float* ah = ab + (size_t)h * L_ * L_;
            float ha = ah[st[0][0] * L_ + l] + ah[st[0][1] * L_ + l]
                     + ah[st[0][2] * L_ + l] + ah[st[0][3] * L_ + l];
            float ta = ah[st[1][0] * L_ + l] + ah[st[1][1] * L_ + l]
                     + ah[st[1][2] * L_ + l] + ah[st[1][3] * L_ + l];
            acc += ha * ta;
        }
        acc *= (0.25f * 0.25f) / (float)HEADS_;
        ht[l]  = acc;
        red[tid] = acc;
    }
    __syncthreads();
    for (int s = 256; s > 0; s >>= 1) {
        if (tid < s) red[tid] += red[tid + s];
        __syncthreads();
    }
    float inv = 1.f / (red[0] + 1e-5f);
    g_HT[b][tid] = ht[tid] * inv;
}

// ---------------------------------------------------------------------------
// K2: rs partials: rs_part[z][b][d] = sum_{l in chunk z} seq[b,l,d] * ht[b,l]
// grid = (B, HID/256, 4), block = 256
// ---------------------------------------------------------------------------
__global__ void k2_rs(const float* __restrict__ seq)
{
    int b = blockIdx.x;
    int d = blockIdx.y * 256 + threadIdx.x;
    int z = blockIdx.z;
    __shared__ float ht[128];
    int l0 = z * 128;
    if (threadIdx.x < 128) ht[threadIdx.x] = g_HT[b][l0 + threadIdx.x];
    __syncthreads();

    const float* p = seq + ((size_t)b * L_ + l0) * HID_ + d;
    float acc = 0.f;
    #pragma unroll 8
    for (int l = 0; l < 128; l++) acc += p[(size_t)l * HID_] * ht[l];
    g_RSp[z][b][d] = acc;
}

// K2b: deterministic 4-way reduce, scatter rs into both concat buffers
__global__ void k2b_reduce()
{
    int i = blockIdx.x * 256 + threadIdx.x;
    int b = i / HID_, d = i - b * HID_;
    float v = g_RSp[0][b][d] + g_RSp[1][b][d] + g_RSp[2][b][d] + g_RSp[3][b][d];
    g_X[0][b][HID_ + d] = v;
    g_X[1][b][HID_ + d] = v;
}

// ---------------------------------------------------------------------------
// K3 v2: warp-per-row GEMV batch. Each warp computes one output row for all
// 16 batches. The row's entire W slice (48 floats/lane) is front-batched into
// registers (24 LDG.64 in flight -> DRAM latency covered); X is read as L1-hot
// float4 LDGs. 16 accumulators/lane give ILP-16 on the FMA chain. No barriers.
// grid = (EMB/4, 2), block = 128 (4 warps = 4 rows)
// ---------------------------------------------------------------------------
__global__ void __launch_bounds__(128) k3_proj(
        const float* __restrict__ Wh, const float* __restrict__ bh,
        const float* __restrict__ Wt, const float* __restrict__ bt)
{
    int e    = blockIdx.y;
    const float* W    = e ? Wt : Wh;
    const float* bias = e ? bt : bh;
    int warp = threadIdx.x >> 5, lane = threadIdx.x & 31;
    int row  = blockIdx.x * 4 + warp;          // 0..767

    const float* wr = W + (size_t)row * XDIM_;
    const float* xb = &g_X[e][0][0];

    // Front-batch the whole W row: 12 chunks of 128 floats (lane*4 each).
    // W rows are 8B-aligned (1542*4 bytes), so use float2 pairs.
    float w[48];
    #pragma unroll
    for (int c = 0; c < 12; c++) {
        int k = c * 128 + lane * 4;
        float2 a  = *(const float2*)(wr + k);
        float2 b2 = *(const float2*)(wr + k + 2);
        w[c * 4 + 0] = a.x;  w[c * 4 + 1] = a.y;
        w[c * 4 + 2] = b2.x; w[c * 4 + 3] = b2.y;
    }

    float acc[16];
    #pragma unroll
    for (int b = 0; b < 16; b++) acc[b] = 0.f;

    #pragma unroll
    for (int c = 0; c < 12; c++) {
        int k = c * 128 + lane * 4;
        #pragma unroll
        for (int b = 0; b < 16; b++) {
            float4 x = *(const float4*)(xb + b * XPAD_ + k);
            acc[b] = fmaf(w[c * 4 + 0], x.x, acc[b]);
            acc[b] = fmaf(w[c * 4 + 1], x.y, acc[b]);
            acc[b] = fmaf(w[c * 4 + 2], x.z, acc[b]);
            acc[b] = fmaf(w[c * 4 + 3], x.w, acc[b]);
        }
    }

    // K tail: k = 1536..1541 handled by lanes 0..5 (summed in the butterfly)
    if (lane < 6) {
        float wt_ = wr[1536 + lane];
        #pragma unroll
        for (int b = 0; b < 16; b++)
            acc[b] = fmaf(wt_, xb[b * XPAD_ + 1536 + lane], acc[b]);
    }

    // Cross-lane reduction: butterfly each accumulator
    #pragma unroll
    for (int b = 0; b < 16; b++) {
        float v = acc[b];
        v += __shfl_xor_sync(0xffffffffu, v, 16);
        v += __shfl_xor_sync(0xffffffffu, v, 8);
        v += __shfl_xor_sync(0xffffffffu, v, 4);
        v += __shfl_xor_sync(0xffffffffu, v, 2);
        v += __shfl_xor_sync(0xffffffffu, v, 1);
        acc[b] = v;
    }

    float bv = bias[row];
    #pragma unroll
    for (int b = 0; b < 16; b++)
        if (lane == b) g_S2[e][b][row] = tanhf(acc[b] + bv);
}

// ---------------------------------------------------------------------------
// K4: fused bilinear outer-product + logits = bl @ Wb.T + bb
// grid = (NCLS, 4 batch-groups), block = 256
// ---------------------------------------------------------------------------
__global__ void k4_logits(const float* __restrict__ Wb, const float* __restrict__ bbias,
                          float* __restrict__ out)
{
    int c  = blockIdx.x;
    int bg = blockIdx.y;
    int tid = threadIdx.x;

    __shared__ float hs[4][EMB_];
    __shared__ float ts[4][EMB_];
    for (int t = tid; t < 4 * EMB_; t += 256) {
        int bi = t / EMB_, d = t - bi * EMB_;
        hs[bi][d] = g_S2[0][bg * 4 + bi][d];
        ts[bi][d] = g_S2[1][bg * 4 + bi][d];
    }
    __syncthreads();

    float a0 = 0.f, a1 = 0.f, a2 = 0.f, a3 = 0.f;
    const float* wr = Wb + (size_t)c * EMB_ * BLK_;
    for (int j = tid; j < EMB_ * BLK_; j += 256) {
        float w = wr[j];
        int g = j >> 6, rem = j & 63, i = rem >> 3, jj = rem & 7;
        int hi = g * 8 + i, ti = g * 8 + jj;
        a0 += w * hs[0][hi] * ts[0][ti];
        a1 += w * hs[1][hi] * ts[1][ti];
        a2 += w * hs[2][hi] * ts[2][ti];
        a3 += w * hs[3][hi] * ts[3][ti];
    }

    __shared__ float red[4][256];
    red[0][tid] = a0; red[1][tid] = a1; red[2][tid] = a2; red[3][tid] = a3;
    __syncthreads();
    for (int s = 128; s > 0; s >>= 1) {
        if (tid < s) {
            red[0][tid] += red[0][tid + s];
            red[1][tid] += red[1][tid + s];
            red[2][tid] += red[2][tid + s];
            red[3][tid] += red[3][tid + s];
        }
        __syncthreads();
    }
    if (tid < 4)
        out[(size_t)(bg * 4 + tid) * NCLS_ + c] = red[tid][0] + bbias[c];
}

// ---------------------------------------------------------------------------
extern "C" void kernel_launch(void* const* d_in, const int* in_sizes, int n_in,
                              void* d_out, int out_size)
{
    const float* seq  = (const float*)d_in[0];
    const float* attn = (const float*)d_in[1];
    const int*   epos = (const int*)  d_in[2];
    const float* hsn  = (const float*)d_in[3];
    const float* tsn  = (const float*)d_in[4];
    const float* Wh   = (const float*)d_in[5];
    const float* bh   = (const float*)d_in[6];
    const float* Wt   = (const float*)d_in[7];
    const float* bt   = (const float*)d_in[8];
    const float* Wb   = (const float*)d_in[9];
    const float* bb   = (const float*)d_in[10];
    float* out = (float*)d_out;

    k1_gather<<<B_, 512>>>(seq, attn, epos, hsn, tsn);
    k2_rs<<<dim3(B_, HID_ / 256, 4), 256>>>(seq);
    k2b_reduce<<<48, 256>>>();
    k3_proj<<<dim3(EMB_ / 4, 2), 128>>>(Wh, bh, Wt, bt);
    k4_logits<<<dim3(NCLS_, 4), 256>>>(Wb, bb, out);
}